// round 11
// baseline (speedup 1.0000x reference)
#include <cuda_runtime.h>

// DynamicTimeStretch: out[t] = (alpha*n[idx+1] + (1-alpha)*n[idx])^2,
// n[j] = |spec[j]|. Phase accumulation cancels under abs()^2.
// Warp-specialized: producer warps (LDG+sqrt+STS) and consumer warps
// (LDS+FMA+STG) run concurrently on a double-buffered norms array.

#define N_ROWS (16 * 513)     // 8208
#define T_IN 2048
#define N_OUT 2276
#define N_OUT4 (N_OUT / 4)    // 569
#define RATE 0.9f
#define THREADS 288
#define N_PROD 128            // warps 0-3: producers
#define N_CONS 160            // warps 4-8: consumers
#define GRID (148 * 4)        // 592 persistent blocks, ~14 rows each

__device__ __forceinline__ void fill_norms(float* __restrict__ nb,
                                           const float* __restrict__ xr,
                                           const float* __restrict__ xi,
                                           int row, int tp)
{
    const float4* r4 = (const float4*)(xr + (long)row * T_IN);
    const float4* i4 = (const float4*)(xi + (long)row * T_IN);
    #pragma unroll
    for (int i = 0; i < 2; i++) {
        const int j0 = tp + (2 * i) * N_PROD;
        const int j1 = tp + (2 * i + 1) * N_PROD;
        // batch 4 LDG.128 before use: MLP 4
        const float4 ra = __ldcs(r4 + j0);
        const float4 ia = __ldcs(i4 + j0);
        const float4 rb = __ldcs(r4 + j1);
        const float4 ib = __ldcs(i4 + j1);
        float4 s;
        s.x = sqrtf(fmaf(ra.x, ra.x, ia.x * ia.x));
        s.y = sqrtf(fmaf(ra.y, ra.y, ia.y * ia.y));
        s.z = sqrtf(fmaf(ra.z, ra.z, ia.z * ia.z));
        s.w = sqrtf(fmaf(ra.w, ra.w, ia.w * ia.w));
        ((float4*)nb)[j0] = s;
        s.x = sqrtf(fmaf(rb.x, rb.x, ib.x * ib.x));
        s.y = sqrtf(fmaf(rb.y, rb.y, ib.y * ib.y));
        s.z = sqrtf(fmaf(rb.z, rb.z, ib.z * ib.z));
        s.w = sqrtf(fmaf(rb.w, rb.w, ib.w * ib.w));
        ((float4*)nb)[j1] = s;
    }
}

__device__ __forceinline__ void consume_row(const float* __restrict__ nb,
                                            float* __restrict__ out,
                                            int row, int tc)
{
    float* orow = out + (long)row * N_OUT;
    // Partial iteration first (o4 in [3*160, 569)), then 3 full iterations.
    {
        const int o4 = tc + 3 * N_CONS;
        if (o4 < N_OUT4) {
            float4 res;
            #pragma unroll
            for (int k = 0; k < 4; k++) {
                const int t = o4 * 4 + k;
                const float ts = (float)t * RATE;
                const int idx = (int)ts;
                const float a = ts - (float)idx;
                const float m = fmaf(a, nb[idx + 1], (1.0f - a) * nb[idx]);
                ((float*)&res)[k] = m * m;
            }
            __stcs((float4*)orow + o4, res);
        }
    }
    #pragma unroll
    for (int v = 0; v < 3; v++) {
        const int o4 = tc + v * N_CONS;
        float4 res;
        #pragma unroll
        for (int k = 0; k < 4; k++) {
            const int t = o4 * 4 + k;
            // Match jax f32 arithmetic exactly
            const float ts = (float)t * RATE;
            const int idx = (int)ts;
            const float a = ts - (float)idx;
            const float m = fmaf(a, nb[idx + 1], (1.0f - a) * nb[idx]);
            ((float*)&res)[k] = m * m;
        }
        __stcs((float4*)orow + o4, res);
    }
}

__global__ void __launch_bounds__(THREADS, 5)
dts_kernel(const float* __restrict__ xr,
           const float* __restrict__ xi,
           float* __restrict__ out)
{
    __shared__ float nbuf[2][T_IN + 4];   // double-buffered norms + sentinel

    const int tid = threadIdx.x;
    const int row0 = blockIdx.x;

    if (tid == 0) { nbuf[0][T_IN] = 0.0f; nbuf[1][T_IN] = 0.0f; }

    // Prologue: producers fill buf 0 with the first row.
    if (tid < N_PROD) fill_norms(nbuf[0], xr, xi, row0, tid);
    __syncthreads();

    int w = 0;
    for (int row = row0; row < N_ROWS; row += GRID, w ^= 1) {
        if (tid < N_PROD) {
            const int nrow = row + GRID;
            if (nrow < N_ROWS)
                fill_norms(nbuf[w ^ 1], xr, xi, nrow, tid);
        } else {
            consume_row(nbuf[w], out, row, tid - N_PROD);
        }
        __syncthreads();
    }
}

extern "C" void kernel_launch(void* const* d_in, const int* in_sizes, int n_in,
                              void* d_out, int out_size)
{
    const float* xr = (const float*)d_in[0];
    const float* xi = (const float*)d_in[1];
    float* out = (float*)d_out;

    dts_kernel<<<GRID, THREADS>>>(xr, xi, out);
}